// round 5
// baseline (speedup 1.0000x reference)
#include <cuda_runtime.h>
#include <cuda_bf16.h>
#include <cstdint>

#define TT   2048
#define DD   64
#define CH   64
#define NC   (TT/CH)    // 32 chunks
#define BH   64         // B*H
#define PIT  72         // smem pitch in bf16 elements (144B rows, ldmatrix conflict-free)
#define TILE_B (DD*PIT*2)  // 9216 bytes per 64x64 bf16 tile

// Exclusive-prefix KV states, fp32: 64 * 32 * 64 * 64 * 4B = 32 MB
__device__ float g_state[(size_t)BH * NC * DD * DD];

// ---------------------------------------------------------------------------
// helpers
// ---------------------------------------------------------------------------
__device__ __forceinline__ uint32_t smem_u32(const void* p) {
    uint32_t a;
    asm("{ .reg .u64 t; cvta.to.shared.u64 t, %1; cvt.u32.u64 %0, t; }" : "=r"(a) : "l"(p));
    return a;
}
__device__ __forceinline__ void ldsm4(uint32_t addr, uint32_t r[4]) {
    asm volatile("ldmatrix.sync.aligned.m8n8.x4.shared.b16 {%0,%1,%2,%3}, [%4];"
                 : "=r"(r[0]), "=r"(r[1]), "=r"(r[2]), "=r"(r[3]) : "r"(addr));
}
__device__ __forceinline__ void ldsm4t(uint32_t addr, uint32_t r[4]) {
    asm volatile("ldmatrix.sync.aligned.m8n8.x4.trans.shared.b16 {%0,%1,%2,%3}, [%4];"
                 : "=r"(r[0]), "=r"(r[1]), "=r"(r[2]), "=r"(r[3]) : "r"(addr));
}
__device__ __forceinline__ void mma16816(float c[4], const uint32_t a[4], uint32_t b0, uint32_t b1) {
    asm volatile(
        "mma.sync.aligned.m16n8k16.row.col.f32.bf16.bf16.f32 "
        "{%0,%1,%2,%3}, {%4,%5,%6,%7}, {%8,%9}, {%0,%1,%2,%3};"
        : "+f"(c[0]), "+f"(c[1]), "+f"(c[2]), "+f"(c[3])
        : "r"(a[0]), "r"(a[1]), "r"(a[2]), "r"(a[3]), "r"(b0), "r"(b1));
}
__device__ __forceinline__ void split_bf(float x, __nv_bfloat16& h, __nv_bfloat16& l) {
    h = __float2bfloat16(x);
    l = __float2bfloat16(x - __bfloat162float(h));
}
__device__ __forceinline__ uint32_t pack2(__nv_bfloat16 a, __nv_bfloat16 b) {
    __nv_bfloat162 v = __halves2bfloat162(a, b);
    return *reinterpret_cast<uint32_t*>(&v);
}
__device__ __forceinline__ void split4(float4 f, uint2& hi, uint2& lo) {
    __nv_bfloat16 h0, l0, h1, l1, h2, l2, h3, l3;
    split_bf(f.x, h0, l0); split_bf(f.y, h1, l1);
    split_bf(f.z, h2, l2); split_bf(f.w, h3, l3);
    hi = make_uint2(pack2(h0, h1), pack2(h2, h3));
    lo = make_uint2(pack2(l0, l1), pack2(l2, l3));
}

// ---------------------------------------------------------------------------
// Kernel 1: KV_c = K_c^T V_c. (unchanged from R4 — near memory floor)
// ---------------------------------------------------------------------------
#define K1_KH 0
#define K1_KL (1*TILE_B)
#define K1_VH (2*TILE_B)
#define K1_VL (3*TILE_B)
#define K1_SMEM (4*TILE_B)

__global__ __launch_bounds__(128, 4) void kv_kernel(const float* __restrict__ kg,
                                                    const float* __restrict__ vg) {
    extern __shared__ char sm[];
    const uint32_t sb = smem_u32(sm);
    const int tid = threadIdx.x, w = tid >> 5, l = tid & 31;
    const int c = blockIdx.x, bh = blockIdx.y;

    const float* kp = kg + ((size_t)bh * TT + (size_t)c * CH) * DD;
    const float* vp = vg + ((size_t)bh * TT + (size_t)c * CH) * DD;

#pragma unroll
    for (int it = 0; it < 8; it++) {
        int idx = tid + it * 128;
        int j = idx >> 4, d0 = (idx & 15) * 4;
        uint2 hi, lo;
        split4(*(const float4*)(kp + (size_t)j * DD + d0), hi, lo);
        *(uint2*)(sm + K1_KH + (j * PIT + d0) * 2) = hi;
        *(uint2*)(sm + K1_KL + (j * PIT + d0) * 2) = lo;
        split4(*(const float4*)(vp + (size_t)j * DD + d0), hi, lo);
        *(uint2*)(sm + K1_VH + (j * PIT + d0) * 2) = hi;
        *(uint2*)(sm + K1_VL + (j * PIT + d0) * 2) = lo;
    }
    __syncthreads();

    const int m0 = (w & 1) * 32, n0 = (w >> 1) * 32;
    const uint32_t aOff = (((l & 7) + ((l >> 4) & 1) * 8) * PIT + m0 + (l & 8)) * 2;
    const uint32_t bOff = (((l & 7) + (l & 8)) * PIT + n0 + ((l >> 4) & 1) * 8) * 2;

    float acc[2][4][4] = {};
    const uint32_t aSel[3] = {K1_KH, K1_KH, K1_KL};
    const uint32_t bSel[3] = {K1_VH, K1_VL, K1_VH};
#pragma unroll
    for (int p = 0; p < 3; p++) {
        const uint32_t aB = sb + aSel[p] + aOff, bB = sb + bSel[p] + bOff;
#pragma unroll
        for (int ks = 0; ks < 4; ks++) {
            const uint32_t ko = ks * 16 * PIT * 2;
            uint32_t a0[4], a1[4], b0[4], b1[4];
            ldsm4t(aB + ko, a0);
            ldsm4t(aB + ko + 32, a1);
            ldsm4t(bB + ko, b0);
            ldsm4t(bB + ko + 32, b1);
            mma16816(acc[0][0], a0, b0[0], b0[1]); mma16816(acc[0][1], a0, b0[2], b0[3]);
            mma16816(acc[0][2], a0, b1[0], b1[1]); mma16816(acc[0][3], a0, b1[2], b1[3]);
            mma16816(acc[1][0], a1, b0[0], b0[1]); mma16816(acc[1][1], a1, b0[2], b0[3]);
            mma16816(acc[1][2], a1, b1[0], b1[1]); mma16816(acc[1][3], a1, b1[2], b1[3]);
        }
    }

    float* outp = g_state + ((size_t)(bh * NC + c)) * (DD * DD);
#pragma unroll
    for (int mi = 0; mi < 2; mi++)
#pragma unroll
        for (int ni = 0; ni < 4; ni++)
#pragma unroll
            for (int half = 0; half < 2; half++) {
                int d = m0 + mi * 16 + (l >> 2) + half * 8;
                int e = n0 + ni * 8 + 2 * (l & 3);
                *(float2*)(outp + (size_t)d * DD + e) =
                    make_float2(acc[mi][ni][2 * half], acc[mi][ni][2 * half + 1]);
            }
}

// ---------------------------------------------------------------------------
// Kernel 2: exclusive prefix — batched loads (MLP=32) then register prefix.
// Thread owns 2 consecutive elements (float2).
// ---------------------------------------------------------------------------
__global__ __launch_bounds__(256) void prefix_kernel() {
    const int e2 = blockIdx.x * 256 + threadIdx.x;   // pair index 0..2047
    const int bh = blockIdx.y;
    const size_t stride = DD * DD;
    float* base = g_state + (size_t)bh * NC * stride + 2 * (size_t)e2;

    float2 vals[NC];
#pragma unroll
    for (int c = 0; c < NC; c++)
        vals[c] = *(const float2*)(base + (size_t)c * stride);

    float2 run = make_float2(0.f, 0.f);
#pragma unroll
    for (int c = 0; c < NC; c++) {
        float2 t = vals[c];
        *(float2*)(base + (size_t)c * stride) = run;
        run.x += t.x;
        run.y += t.y;
    }
}

// ---------------------------------------------------------------------------
// Kernel 3: P = tril(Q K^T); O = Q S + P V.  Register-reduced: P computed in
// two n32 halves, only 2 live P fragment blocks at a time.
// ---------------------------------------------------------------------------
#define K3_QH 0
#define K3_QL (1*TILE_B)
#define K3_KH (2*TILE_B)
#define K3_KL (3*TILE_B)
#define K3_VH (4*TILE_B)
#define K3_VL (5*TILE_B)
#define K3_SH (6*TILE_B)
#define K3_SL (7*TILE_B)
#define K3_SMEM (8*TILE_B)

__global__ __launch_bounds__(128, 3) void out_kernel(const float* __restrict__ qg,
                                                     const float* __restrict__ kg,
                                                     const float* __restrict__ vg,
                                                     float* __restrict__ og) {
    extern __shared__ char sm[];
    const uint32_t sb = smem_u32(sm);
    const int tid = threadIdx.x, w = tid >> 5, l = tid & 31;
    const int c = blockIdx.x, bh = blockIdx.y;

    const float* qp = qg + ((size_t)bh * TT + (size_t)c * CH) * DD;
    const float* kp = kg + ((size_t)bh * TT + (size_t)c * CH) * DD;
    const float* vp = vg + ((size_t)bh * TT + (size_t)c * CH) * DD;
    const float* sp = g_state + ((size_t)(bh * NC + c)) * (DD * DD);

#pragma unroll
    for (int it = 0; it < 8; it++) {
        int idx = tid + it * 128;
        int r = idx >> 4, d0 = (idx & 15) * 4;
        const uint32_t so = (r * PIT + d0) * 2;
        uint2 hi, lo;
        split4(*(const float4*)(qp + (size_t)r * DD + d0), hi, lo);
        *(uint2*)(sm + K3_QH + so) = hi;  *(uint2*)(sm + K3_QL + so) = lo;
        split4(*(const float4*)(kp + (size_t)r * DD + d0), hi, lo);
        *(uint2*)(sm + K3_KH + so) = hi;  *(uint2*)(sm + K3_KL + so) = lo;
        split4(*(const float4*)(vp + (size_t)r * DD + d0), hi, lo);
        *(uint2*)(sm + K3_VH + so) = hi;  *(uint2*)(sm + K3_VL + so) = lo;
        split4(*(const float4*)(sp + (size_t)r * DD + d0), hi, lo);
        *(uint2*)(sm + K3_SH + so) = hi;  *(uint2*)(sm + K3_SL + so) = lo;
    }
    __syncthreads();

    const int m0 = w * 16;
    const int gid = l >> 2, tig = l & 3;
    const int i0 = m0 + gid;
    const uint32_t aOffN = ((m0 + (l & 15)) * PIT + ((l >> 4) << 3)) * 2;
    const uint32_t bOffN = (((l & 7) + ((l & 16) >> 1)) * PIT + ((l >> 3) & 1) * 8) * 2;
    const uint32_t bOffT = (((l & 7) + (l & 8)) * PIT + ((l >> 4) & 1) * 8) * 2;

    // ---- O1 = Q @ S (B = S^T via trans loads of S[d][e]) ----
    float accO[8][4] = {};
    {
        const uint32_t aS[3] = {K3_QH, K3_QH, K3_QL};
        const uint32_t bS[3] = {K3_SH, K3_SL, K3_SH};
#pragma unroll
        for (int p = 0; p < 3; p++) {
            const uint32_t aB = sb + aS[p] + aOffN, bB = sb + bS[p] + bOffT;
#pragma unroll
            for (int ks = 0; ks < 4; ks++) {
                uint32_t a[4];
                ldsm4(aB + ks * 32, a);
#pragma unroll
                for (int nb = 0; nb < 4; nb++) {
                    uint32_t b[4];
                    ldsm4t(bB + ks * 16 * PIT * 2 + nb * 32, b);
                    mma16816(accO[2 * nb],     a, b[0], b[1]);
                    mma16816(accO[2 * nb + 1], a, b[2], b[3]);
                }
            }
        }
    }

    // ---- P + O2 in two n32 halves (register-lean) ----
#pragma unroll
    for (int hb = 0; hb < 2; hb++) {
        if (w < 2 * hb) break;   // whole half above diagonal for this warp

        // P half: A=Q [m][k], B=K [j][k]
        float accP[2][2][4] = {};   // [nb2][n8sub][4]
        {
            const uint32_t aS[3] = {K3_QH, K3_QH, K3_QL};
            const uint32_t bS[3] = {K3_KH, K3_KL, K3_KH};
#pragma unroll
            for (int p = 0; p < 3; p++) {
                const uint32_t aB = sb + aS[p] + aOffN, bB = sb + bS[p] + bOffN;
#pragma unroll
                for (int ks = 0; ks < 4; ks++) {
                    uint32_t a[4];
                    ldsm4(aB + ks * 32, a);
#pragma unroll
                    for (int nb2 = 0; nb2 < 2; nb2++) {
                        const int nb = 2 * hb + nb2;
                        if (nb <= w) {
                            uint32_t b[4];
                            ldsm4(bB + nb * 16 * PIT * 2 + ks * 32, b);
                            mma16816(accP[nb2][0], a, b[0], b[1]);
                            mma16816(accP[nb2][1], a, b[2], b[3]);
                        }
                    }
                }
            }
        }

        // mask + in-register split to A-operand fragments (2 live blocks)
        uint32_t aPh[2][4], aPl[2][4];
#pragma unroll
        for (int nb2 = 0; nb2 < 2; nb2++) {
            const int nb = 2 * hb + nb2;
            if (nb <= w) {
#pragma unroll
                for (int s2 = 0; s2 < 2; s2++) {
                    const int j0 = 16 * nb + 8 * s2 + 2 * tig;
                    float c0 = (j0     <= i0)     ? accP[nb2][s2][0] : 0.f;
                    float c1 = (j0 + 1 <= i0)     ? accP[nb2][s2][1] : 0.f;
                    float c2 = (j0     <= i0 + 8) ? accP[nb2][s2][2] : 0.f;
                    float c3 = (j0 + 1 <= i0 + 8) ? accP[nb2][s2][3] : 0.f;
                    __nv_bfloat16 h0, l0, h1, l1, h2, l2, h3, l3;
                    split_bf(c0, h0, l0); split_bf(c1, h1, l1);
                    split_bf(c2, h2, l2); split_bf(c3, h3, l3);
                    aPh[nb2][2 * s2]     = pack2(h0, h1);
                    aPh[nb2][2 * s2 + 1] = pack2(h2, h3);
                    aPl[nb2][2 * s2]     = pack2(l0, l1);
                    aPl[nb2][2 * s2 + 1] = pack2(l2, l3);
                }
            }
        }

        // O2 += P @ V for this half's kb blocks (B = V^T trans)
#pragma unroll
        for (int p = 0; p < 3; p++) {
            const uint32_t bB = sb + (p == 1 ? K3_VL : K3_VH) + bOffT;
#pragma unroll
            for (int kb2 = 0; kb2 < 2; kb2++) {
                const int kb = 2 * hb + kb2;
                if (kb <= w) {
                    const uint32_t (&a)[4] = (p < 2) ? aPh[kb2] : aPl[kb2];
#pragma unroll
                    for (int nb = 0; nb < 4; nb++) {
                        uint32_t b[4];
                        ldsm4t(bB + kb * 16 * PIT * 2 + nb * 32, b);
                        mma16816(accO[2 * nb],     a, b[0], b[1]);
                        mma16816(accO[2 * nb + 1], a, b[2], b[3]);
                    }
                }
            }
        }
    }

    // ---- store O ----
    float* op = og + ((size_t)bh * TT + (size_t)c * CH) * DD;
#pragma unroll
    for (int nb8 = 0; nb8 < 8; nb8++) {
        const int e = 8 * nb8 + 2 * tig;
        *(float2*)(op + (size_t)i0 * DD + e)       = make_float2(accO[nb8][0], accO[nb8][1]);
        *(float2*)(op + (size_t)(i0 + 8) * DD + e) = make_float2(accO[nb8][2], accO[nb8][3]);
    }
}

// ---------------------------------------------------------------------------
extern "C" void kernel_launch(void* const* d_in, const int* in_sizes, int n_in,
                              void* d_out, int out_size) {
    const float* q = (const float*)d_in[0];
    const float* k = (const float*)d_in[1];
    const float* v = (const float*)d_in[2];
    float* o = (float*)d_out;

    cudaFuncSetAttribute(kv_kernel, cudaFuncAttributeMaxDynamicSharedMemorySize, K1_SMEM);
    cudaFuncSetAttribute(out_kernel, cudaFuncAttributeMaxDynamicSharedMemorySize, K3_SMEM);

    dim3 grid(NC, BH);
    kv_kernel<<<grid, 128, K1_SMEM>>>(k, v);
    prefix_kernel<<<dim3((DD * DD / 2) / 256, BH), 256>>>();
    out_kernel<<<grid, 128, K3_SMEM>>>(q, k, v, o);
}

// round 6
// speedup vs baseline: 1.0360x; 1.0360x over previous
#include <cuda_runtime.h>
#include <cuda_bf16.h>
#include <cstdint>

#define TT   2048
#define DD   64
#define CH   64
#define NC   (TT/CH)    // 32 chunks
#define BH   64         // B*H
#define PIT  72         // smem pitch in bf16 elements (144B rows, ldmatrix conflict-free)
#define TILE_B (DD*PIT*2)  // 9216 bytes per 64x64 bf16 tile

// Exclusive-prefix KV states, fp32: 64 * 32 * 64 * 64 * 4B = 32 MB
__device__ float g_state[(size_t)BH * NC * DD * DD];

// ---------------------------------------------------------------------------
// helpers
// ---------------------------------------------------------------------------
__device__ __forceinline__ uint32_t smem_u32(const void* p) {
    uint32_t a;
    asm("{ .reg .u64 t; cvta.to.shared.u64 t, %1; cvt.u32.u64 %0, t; }" : "=r"(a) : "l"(p));
    return a;
}
__device__ __forceinline__ void ldsm4(uint32_t addr, uint32_t r[4]) {
    asm volatile("ldmatrix.sync.aligned.m8n8.x4.shared.b16 {%0,%1,%2,%3}, [%4];"
                 : "=r"(r[0]), "=r"(r[1]), "=r"(r[2]), "=r"(r[3]) : "r"(addr));
}
__device__ __forceinline__ void ldsm4t(uint32_t addr, uint32_t r[4]) {
    asm volatile("ldmatrix.sync.aligned.m8n8.x4.trans.shared.b16 {%0,%1,%2,%3}, [%4];"
                 : "=r"(r[0]), "=r"(r[1]), "=r"(r[2]), "=r"(r[3]) : "r"(addr));
}
__device__ __forceinline__ void mma16816(float c[4], const uint32_t a[4], uint32_t b0, uint32_t b1) {
    asm volatile(
        "mma.sync.aligned.m16n8k16.row.col.f32.bf16.bf16.f32 "
        "{%0,%1,%2,%3}, {%4,%5,%6,%7}, {%8,%9}, {%0,%1,%2,%3};"
        : "+f"(c[0]), "+f"(c[1]), "+f"(c[2]), "+f"(c[3])
        : "r"(a[0]), "r"(a[1]), "r"(a[2]), "r"(a[3]), "r"(b0), "r"(b1));
}
__device__ __forceinline__ void split_bf(float x, __nv_bfloat16& h, __nv_bfloat16& l) {
    h = __float2bfloat16(x);
    l = __float2bfloat16(x - __bfloat162float(h));
}
__device__ __forceinline__ uint32_t pack2(__nv_bfloat16 a, __nv_bfloat16 b) {
    __nv_bfloat162 v = __halves2bfloat162(a, b);
    return *reinterpret_cast<uint32_t*>(&v);
}
__device__ __forceinline__ void split4(float4 f, uint2& hi, uint2& lo) {
    __nv_bfloat16 h0, l0, h1, l1, h2, l2, h3, l3;
    split_bf(f.x, h0, l0); split_bf(f.y, h1, l1);
    split_bf(f.z, h2, l2); split_bf(f.w, h3, l3);
    hi = make_uint2(pack2(h0, h1), pack2(h2, h3));
    lo = make_uint2(pack2(l0, l1), pack2(l2, l3));
}

// ---------------------------------------------------------------------------
// Kernel 1: KV_c = K_c^T V_c. A = K^T via trans-ldmatrix of row-major K[j][d],
// B = V^T via trans-ldmatrix of row-major V[j][e]. Warp quadrants 32x32.
// ---------------------------------------------------------------------------
#define K1_KH 0
#define K1_KL (1*TILE_B)
#define K1_VH (2*TILE_B)
#define K1_VL (3*TILE_B)
#define K1_SMEM (4*TILE_B)

__global__ __launch_bounds__(128) void kv_kernel(const float* __restrict__ kg,
                                                 const float* __restrict__ vg) {
    extern __shared__ char sm[];
    const uint32_t sb = smem_u32(sm);
    const int tid = threadIdx.x, w = tid >> 5, l = tid & 31;
    const int c = blockIdx.x, bh = blockIdx.y;

    const float* kp = kg + ((size_t)bh * TT + (size_t)c * CH) * DD;
    const float* vp = vg + ((size_t)bh * TT + (size_t)c * CH) * DD;

#pragma unroll
    for (int it = 0; it < 8; it++) {
        int idx = tid + it * 128;
        int j = idx >> 4, d0 = (idx & 15) * 4;
        uint2 hi, lo;
        split4(*(const float4*)(kp + (size_t)j * DD + d0), hi, lo);
        *(uint2*)(sm + K1_KH + (j * PIT + d0) * 2) = hi;
        *(uint2*)(sm + K1_KL + (j * PIT + d0) * 2) = lo;
        split4(*(const float4*)(vp + (size_t)j * DD + d0), hi, lo);
        *(uint2*)(sm + K1_VH + (j * PIT + d0) * 2) = hi;
        *(uint2*)(sm + K1_VL + (j * PIT + d0) * 2) = lo;
    }
    __syncthreads();

    const int m0 = (w & 1) * 32, n0 = (w >> 1) * 32;
    const uint32_t aOff = (((l & 7) + ((l >> 4) & 1) * 8) * PIT + m0 + (l & 8)) * 2;
    const uint32_t bOff = (((l & 7) + (l & 8)) * PIT + n0 + ((l >> 4) & 1) * 8) * 2;

    float acc[2][4][4] = {};
    const uint32_t aSel[3] = {K1_KH, K1_KH, K1_KL};
    const uint32_t bSel[3] = {K1_VH, K1_VL, K1_VH};
#pragma unroll
    for (int p = 0; p < 3; p++) {
        const uint32_t aB = sb + aSel[p] + aOff, bB = sb + bSel[p] + bOff;
#pragma unroll
        for (int ks = 0; ks < 4; ks++) {
            const uint32_t ko = ks * 16 * PIT * 2;
            uint32_t a0[4], a1[4], b0[4], b1[4];
            ldsm4t(aB + ko, a0);
            ldsm4t(aB + ko + 32, a1);   // m0+16
            ldsm4t(bB + ko, b0);
            ldsm4t(bB + ko + 32, b1);   // n0+16
            mma16816(acc[0][0], a0, b0[0], b0[1]); mma16816(acc[0][1], a0, b0[2], b0[3]);
            mma16816(acc[0][2], a0, b1[0], b1[1]); mma16816(acc[0][3], a0, b1[2], b1[3]);
            mma16816(acc[1][0], a1, b0[0], b0[1]); mma16816(acc[1][1], a1, b0[2], b0[3]);
            mma16816(acc[1][2], a1, b1[0], b1[1]); mma16816(acc[1][3], a1, b1[2], b1[3]);
        }
    }

    float* outp = g_state + ((size_t)(bh * NC + c)) * (DD * DD);
#pragma unroll
    for (int mi = 0; mi < 2; mi++)
#pragma unroll
        for (int ni = 0; ni < 4; ni++)
#pragma unroll
            for (int half = 0; half < 2; half++) {
                int d = m0 + mi * 16 + (l >> 2) + half * 8;
                int e = n0 + ni * 8 + 2 * (l & 3);
                *(float2*)(outp + (size_t)d * DD + e) =
                    make_float2(acc[mi][ni][2 * half], acc[mi][ni][2 * half + 1]);
            }
}

// ---------------------------------------------------------------------------
// Kernel 2: exclusive prefix — batched loads (MLP=32) then register prefix.
// ---------------------------------------------------------------------------
__global__ __launch_bounds__(256) void prefix_kernel() {
    const int e2 = blockIdx.x * 256 + threadIdx.x;   // pair index 0..2047
    const int bh = blockIdx.y;
    const size_t stride = DD * DD;
    float* base = g_state + (size_t)bh * NC * stride + 2 * (size_t)e2;

    float2 vals[NC];
#pragma unroll
    for (int c = 0; c < NC; c++)
        vals[c] = *(const float2*)(base + (size_t)c * stride);

    float2 run = make_float2(0.f, 0.f);
#pragma unroll
    for (int c = 0; c < NC; c++) {
        float2 t = vals[c];
        *(float2*)(base + (size_t)c * stride) = run;
        run.x += t.x;
        run.y += t.y;
    }
}

// ---------------------------------------------------------------------------
// Kernel 3 (R4-proven structure): P = tril(Q K^T); O = Q S + P V.
// Row-stripe warps (16 rows each), P in registers, causal MMA skipping.
// ---------------------------------------------------------------------------
#define K3_QH 0
#define K3_QL (1*TILE_B)
#define K3_KH (2*TILE_B)
#define K3_KL (3*TILE_B)
#define K3_VH (4*TILE_B)
#define K3_VL (5*TILE_B)
#define K3_SH (6*TILE_B)
#define K3_SL (7*TILE_B)
#define K3_SMEM (8*TILE_B)

__global__ __launch_bounds__(128) void out_kernel(const float* __restrict__ qg,
                                                  const float* __restrict__ kg,
                                                  const float* __restrict__ vg,
                                                  float* __restrict__ og) {
    extern __shared__ char sm[];
    const uint32_t sb = smem_u32(sm);
    const int tid = threadIdx.x, w = tid >> 5, l = tid & 31;
    const int c = blockIdx.x, bh = blockIdx.y;

    const float* qp = qg + ((size_t)bh * TT + (size_t)c * CH) * DD;
    const float* kp = kg + ((size_t)bh * TT + (size_t)c * CH) * DD;
    const float* vp = vg + ((size_t)bh * TT + (size_t)c * CH) * DD;
    const float* sp = g_state + ((size_t)(bh * NC + c)) * (DD * DD);

#pragma unroll
    for (int it = 0; it < 8; it++) {
        int idx = tid + it * 128;
        int r = idx >> 4, d0 = (idx & 15) * 4;
        const uint32_t so = (r * PIT + d0) * 2;
        uint2 hi, lo;
        split4(*(const float4*)(qp + (size_t)r * DD + d0), hi, lo);
        *(uint2*)(sm + K3_QH + so) = hi;  *(uint2*)(sm + K3_QL + so) = lo;
        split4(*(const float4*)(kp + (size_t)r * DD + d0), hi, lo);
        *(uint2*)(sm + K3_KH + so) = hi;  *(uint2*)(sm + K3_KL + so) = lo;
        split4(*(const float4*)(vp + (size_t)r * DD + d0), hi, lo);
        *(uint2*)(sm + K3_VH + so) = hi;  *(uint2*)(sm + K3_VL + so) = lo;
        split4(*(const float4*)(sp + (size_t)r * DD + d0), hi, lo);
        *(uint2*)(sm + K3_SH + so) = hi;  *(uint2*)(sm + K3_SL + so) = lo;
    }
    __syncthreads();

    const int m0 = w * 16;
    const int gid = l >> 2, tig = l & 3;
    const uint32_t aOffN = ((m0 + (l & 15)) * PIT + ((l >> 4) << 3)) * 2;
    const uint32_t bOffN = (((l & 7) + ((l & 16) >> 1)) * PIT + ((l >> 3) & 1) * 8) * 2;
    const uint32_t bOffT = (((l & 7) + (l & 8)) * PIT + ((l >> 4) & 1) * 8) * 2;

    // ---- P = Q K^T (causal: only n-blocks j <= 16(w+1)) ----
    float accP[8][4] = {};
    {
        const uint32_t aS[3] = {K3_QH, K3_QH, K3_QL};
        const uint32_t bS[3] = {K3_KH, K3_KL, K3_KH};
#pragma unroll
        for (int p = 0; p < 3; p++) {
            const uint32_t aB = sb + aS[p] + aOffN, bB = sb + bS[p] + bOffN;
#pragma unroll
            for (int ks = 0; ks < 4; ks++) {
                uint32_t a[4];
                ldsm4(aB + ks * 32, a);
#pragma unroll
                for (int nb = 0; nb < 4; nb++)
                    if (nb <= w) {
                        uint32_t b[4];
                        ldsm4(bB + nb * 16 * PIT * 2 + ks * 32, b);
                        mma16816(accP[2 * nb],     a, b[0], b[1]);
                        mma16816(accP[2 * nb + 1], a, b[2], b[3]);
                    }
            }
        }
    }

    // ---- mask + in-register split to A-operand fragments ----
    uint32_t aPh[4][4], aPl[4][4];
    const int i0 = m0 + gid;
#pragma unroll
    for (int nb = 0; nb < 4; nb++)
        if (nb <= w) {
#pragma unroll
            for (int s2 = 0; s2 < 2; s2++) {
                const int j0 = 16 * nb + 8 * s2 + 2 * tig;
                float c0 = (j0     <= i0)     ? accP[2 * nb + s2][0] : 0.f;
                float c1 = (j0 + 1 <= i0)     ? accP[2 * nb + s2][1] : 0.f;
                float c2 = (j0     <= i0 + 8) ? accP[2 * nb + s2][2] : 0.f;
                float c3 = (j0 + 1 <= i0 + 8) ? accP[2 * nb + s2][3] : 0.f;
                __nv_bfloat16 h0, l0, h1, l1, h2, l2, h3, l3;
                split_bf(c0, h0, l0); split_bf(c1, h1, l1);
                split_bf(c2, h2, l2); split_bf(c3, h3, l3);
                aPh[nb][2 * s2]     = pack2(h0, h1);
                aPh[nb][2 * s2 + 1] = pack2(h2, h3);
                aPl[nb][2 * s2]     = pack2(l0, l1);
                aPl[nb][2 * s2 + 1] = pack2(l2, l3);
            }
        }

    // ---- O1 = Q @ S (B = S^T via trans loads of S[d][e]) ----
    float accO[8][4] = {};
    {
        const uint32_t aS[3] = {K3_QH, K3_QH, K3_QL};
        const uint32_t bS[3] = {K3_SH, K3_SL, K3_SH};
#pragma unroll
        for (int p = 0; p < 3; p++) {
            const uint32_t aB = sb + aS[p] + aOffN, bB = sb + bS[p] + bOffT;
#pragma unroll
            for (int ks = 0; ks < 4; ks++) {
                uint32_t a[4];
                ldsm4(aB + ks * 32, a);
#pragma unroll
                for (int nb = 0; nb < 4; nb++) {
                    uint32_t b[4];
                    ldsm4t(bB + ks * 16 * PIT * 2 + nb * 32, b);
                    mma16816(accO[2 * nb],     a, b[0], b[1]);
                    mma16816(accO[2 * nb + 1], a, b[2], b[3]);
                }
            }
        }
    }

    // ---- O2 += P @ V (A = register P, B = V^T trans; causal k-blocks only) ----
    {
#pragma unroll
        for (int p = 0; p < 3; p++) {
            const uint32_t bB = sb + (p == 1 ? K3_VL : K3_VH) + bOffT;
#pragma unroll
            for (int kb = 0; kb < 4; kb++)
                if (kb <= w) {
                    const uint32_t (&a)[4] = (p < 2) ? aPh[kb] : aPl[kb];
#pragma unroll
                    for (int nb = 0; nb < 4; nb++) {
                        uint32_t b[4];
                        ldsm4t(bB + kb * 16 * PIT * 2 + nb * 32, b);
                        mma16816(accO[2 * nb],     a, b[0], b[1]);
                        mma16816(accO[2 * nb + 1], a, b[2], b[3]);
                    }
                }
        }
    }

    // ---- store O ----
    float* op = og + ((size_t)bh * TT + (size_t)c * CH) * DD;
#pragma unroll
    for (int nb8 = 0; nb8 < 8; nb8++) {
        const int e = 8 * nb8 + 2 * tig;
        *(float2*)(op + (size_t)i0 * DD + e)       = make_float2(accO[nb8][0], accO[nb8][1]);
        *(float2*)(op + (size_t)(i0 + 8) * DD + e) = make_float2(accO[nb8][2], accO[nb8][3]);
    }
}

// ---------------------------------------------------------------------------
extern "C" void kernel_launch(void* const* d_in, const int* in_sizes, int n_in,
                              void* d_out, int out_size) {
    const float* q = (const float*)d_in[0];
    const float* k = (const float*)d_in[1];
    const float* v = (const float*)d_in[2];
    float* o = (float*)d_out;

    cudaFuncSetAttribute(kv_kernel, cudaFuncAttributeMaxDynamicSharedMemorySize, K1_SMEM);
    cudaFuncSetAttribute(out_kernel, cudaFuncAttributeMaxDynamicSharedMemorySize, K3_SMEM);

    dim3 grid(NC, BH);
    kv_kernel<<<grid, 128, K1_SMEM>>>(k, v);
    prefix_kernel<<<dim3((DD * DD / 2) / 256, BH), 256>>>();
    out_kernel<<<grid, 128, K3_SMEM>>>(q, k, v, o);
}